// round 8
// baseline (speedup 1.0000x reference)
#include <cuda_runtime.h>

// Problem constants
#define BATCH   4
#define S_LEN   2048
#define HID     2048
#define HEADS   16
#define DHEAD   128
#define MROWS   (BATCH * S_LEN)        // 8192
#define OUT_ELEMS   ((size_t)BATCH * S_LEN * HID)          // 16777216
#define KV_ELEMS    ((size_t)BATCH * HEADS * 2 * S_LEN * DHEAD) // 33554432

// Scratch (device globals: allocation-free per harness rules)
__device__ float g_qbuf[MROWS * HID];   // 64 MB: scaled Q, [B*S, H*D]
__device__ float g_ctx [MROWS * HID];   // 64 MB: attention context, [B*S, H*D]
__device__ float g_kvbuf[KV_ELEMS];     // 128 MB: KV fallback if d_out doesn't hold the cache

enum { MODE_Q = 0, MODE_K = 1, MODE_V = 2, MODE_O = 3 };

// ---------------------------------------------------------------------------
// NT SGEMM: C[M,N] = A[M,K] * B[N,K]^T,  M=8192, N=K=2048.
// 128x128 tile, BK=8, 256 threads, 8x8 per-thread.
// Double-buffered smem: ONE __syncthreads per k-tile; global prefetch into
// registers overlaps compute, STS into the idle buffer overlaps other warps'
// FFMA tail.
// Epilogue varies by mode (Q-scale / KV-cache remap / plain).
// ---------------------------------------------------------------------------
__global__ __launch_bounds__(256, 2) void gemm_nt(const float* __restrict__ Ain,
                                                  const float* __restrict__ Bw,
                                                  float* __restrict__ outp,
                                                  int mode)
{
    const float* A = (mode == MODE_O) ? g_ctx : Ain;

    __shared__ __align__(16) float As[2][8][128];
    __shared__ __align__(16) float Bs[2][8][128];

    const int tid = threadIdx.x;
    const int m0 = blockIdx.y * 128;
    const int n0 = blockIdx.x * 128;

    const int lrow = tid >> 1;          // 0..127
    const int lcol = (tid & 1) * 4;     // 0 or 4
    const float* Aptr = A  + (size_t)(m0 + lrow) * HID + lcol;
    const float* Bptr = Bw + (size_t)(n0 + lrow) * HID + lcol;

    // Preload k-tile 0 and commit to buffer 0.
    float4 an = *(const float4*)Aptr;
    float4 bn = *(const float4*)Bptr;
    As[0][lcol + 0][lrow] = an.x; As[0][lcol + 1][lrow] = an.y;
    As[0][lcol + 2][lrow] = an.z; As[0][lcol + 3][lrow] = an.w;
    Bs[0][lcol + 0][lrow] = bn.x; Bs[0][lcol + 1][lrow] = bn.y;
    Bs[0][lcol + 2][lrow] = bn.z; Bs[0][lcol + 3][lrow] = bn.w;
    __syncthreads();

    float acc[8][8];
#pragma unroll
    for (int i = 0; i < 8; i++)
#pragma unroll
        for (int j = 0; j < 8; j++) acc[i][j] = 0.f;

    const int ty = tid >> 4;   // 0..15
    const int tx = tid & 15;   // 0..15
    const int NT = HID / 8;    // 256

    for (int kt = 0; kt < NT; ++kt) {
        const int cur = kt & 1;

        // Issue next tile's global loads early (latency hidden by FFMA block).
        if (kt + 1 < NT) {
            an = *(const float4*)(Aptr + (size_t)(kt + 1) * 8);
            bn = *(const float4*)(Bptr + (size_t)(kt + 1) * 8);
        }

#pragma unroll
        for (int k = 0; k < 8; ++k) {
            float4 a0 = *(const float4*)&As[cur][k][ty * 8];
            float4 a1 = *(const float4*)&As[cur][k][ty * 8 + 4];
            float4 b0 = *(const float4*)&Bs[cur][k][tx * 8];
            float4 b1 = *(const float4*)&Bs[cur][k][tx * 8 + 4];
            float av[8] = {a0.x, a0.y, a0.z, a0.w, a1.x, a1.y, a1.z, a1.w};
            float bv[8] = {b0.x, b0.y, b0.z, b0.w, b1.x, b1.y, b1.z, b1.w};
#pragma unroll
            for (int i = 0; i < 8; i++)
#pragma unroll
                for (int j = 0; j < 8; j++)
                    acc[i][j] += av[i] * bv[j];
        }

        // Store next tile into the idle buffer; one barrier per iteration.
        if (kt + 1 < NT) {
            const int nxt = cur ^ 1;
            As[nxt][lcol + 0][lrow] = an.x; As[nxt][lcol + 1][lrow] = an.y;
            As[nxt][lcol + 2][lrow] = an.z; As[nxt][lcol + 3][lrow] = an.w;
            Bs[nxt][lcol + 0][lrow] = bn.x; Bs[nxt][lcol + 1][lrow] = bn.y;
            Bs[nxt][lcol + 2][lrow] = bn.z; Bs[nxt][lcol + 3][lrow] = bn.w;
            __syncthreads();
        }
    }

    const int mbase = m0 + ty * 8;
    const int nbase = n0 + tx * 8;

    if (mode == MODE_Q) {
        // Fold softmax scale and log2(e) into Q so attention uses exp2f.
        const float qs = 0.08838834764831845f * 1.4426950408889634f;
#pragma unroll
        for (int i = 0; i < 8; i++) {
            float* dst = &g_qbuf[(size_t)(mbase + i) * HID + nbase];
            *(float4*)dst       = make_float4(acc[i][0]*qs, acc[i][1]*qs, acc[i][2]*qs, acc[i][3]*qs);
            *(float4*)(dst + 4) = make_float4(acc[i][4]*qs, acc[i][5]*qs, acc[i][6]*qs, acc[i][7]*qs);
        }
    } else if (mode == MODE_O) {
#pragma unroll
        for (int i = 0; i < 8; i++) {
            float* dst = outp + (size_t)(mbase + i) * HID + nbase;
            *(float4*)dst       = make_float4(acc[i][0], acc[i][1], acc[i][2], acc[i][3]);
            *(float4*)(dst + 4) = make_float4(acc[i][4], acc[i][5], acc[i][6], acc[i][7]);
        }
    } else {
        // KV cache layout [B, H, 2, S, D]; row m = b*S+s, col n = h*D+d.
        float* kvout = outp ? outp : g_kvbuf;
        const int cv = (mode == MODE_V) ? 1 : 0;
        const int hh = nbase >> 7;
        const int dd = nbase & 127;
#pragma unroll
        for (int i = 0; i < 8; i++) {
            int m  = mbase + i;
            int bb = m >> 11;
            int ss = m & 2047;
            float* dst = kvout +
                (((size_t)(bb * HEADS + hh) * 2 + cv) * S_LEN + ss) * DHEAD + dd;
            *(float4*)dst       = make_float4(acc[i][0], acc[i][1], acc[i][2], acc[i][3]);
            *(float4*)(dst + 4) = make_float4(acc[i][4], acc[i][5], acc[i][6], acc[i][7]);
        }
    }
}

// ---------------------------------------------------------------------------
// Flash attention (causal, online softmax in base 2, scale pre-folded into Q).
// 64x64 tiles, D=128, 256 threads (8 warps). Warp w owns q-rows 8w..8w+7.
// Row reductions stay inside one warp (shuffles).
// ---------------------------------------------------------------------------
#define KSTR 132                       // padded K/V row stride (floats)
#define PSTR 68                        // padded P row stride (floats)
#define QS_OFF 0
#define KS_OFF (64 * 128)
#define VS_OFF (KS_OFF + 64 * KSTR)
#define PS_OFF (VS_OFF + 64 * KSTR)
#define SMEM_FLOATS (PS_OFF + 64 * PSTR)   // 29440 floats = 117760 bytes

__global__ __launch_bounds__(256) void flash_attn(const float* __restrict__ kvsrc)
{
    extern __shared__ float sm[];
    float* Qs = sm + QS_OFF;
    float* Ks = sm + KS_OFF;
    float* Vs = sm + VS_OFF;
    float* Ps = sm + PS_OFF;

    const float* kvbase = kvsrc ? kvsrc : g_kvbuf;

    const int qt   = blockIdx.x;   // 0..31
    const int h    = blockIdx.y;   // 0..15
    const int b    = blockIdx.z;   // 0..3
    const int tid  = threadIdx.x;
    const int warp = tid >> 5;
    const int lane = tid & 31;
    const int r0   = warp * 8;     // this warp's local q rows

    const float* Qg = g_qbuf + ((size_t)(b * S_LEN + qt * 64) * HID + h * DHEAD);
    const float* Kg = kvbase + ((size_t)(b * HEADS + h) * 2 + 0) * S_LEN * DHEAD;
    const float* Vg = kvbase + ((size_t)(b * HEADS + h) * 2 + 1) * S_LEN * DHEAD;

    // Load Q tile [64][128]
    for (int i = tid; i < 64 * 32; i += 256) {
        int r = i >> 5, c4 = i & 31;
        *(float4*)&Qs[r * 128 + c4 * 4] = *(const float4*)(Qg + (size_t)r * HID + c4 * 4);
    }

    float o[8][4];
    float mrow[8], lrow[8];
#pragma unroll
    for (int i = 0; i < 8; i++) {
        mrow[i] = -1e30f; lrow[i] = 0.f;
        o[i][0] = o[i][1] = o[i][2] = o[i][3] = 0.f;
    }
    __syncthreads();

    for (int kt = 0; kt <= qt; ++kt) {
        const int kbase = kt * 64;
        // Load K,V tiles [64][128]
        for (int i = tid; i < 64 * 32; i += 256) {
            int r = i >> 5, c4 = i & 31;
            *(float4*)&Ks[r * KSTR + c4 * 4] =
                *(const float4*)(Kg + (size_t)(kbase + r) * DHEAD + c4 * 4);
            *(float4*)&Vs[r * KSTR + c4 * 4] =
                *(const float4*)(Vg + (size_t)(kbase + r) * DHEAD + c4 * 4);
        }
        __syncthreads();

        // GEMM1: S = Qs * Ks^T. Lane owns k-cols {lane, lane+32}.
        float sv[8][2];
#pragma unroll
        for (int i = 0; i < 8; i++) sv[i][0] = sv[i][1] = 0.f;

#pragma unroll 4
        for (int k = 0; k < DHEAD; k += 4) {
            float4 k0 = *(const float4*)&Ks[lane * KSTR + k];
            float4 k1 = *(const float4*)&Ks[(lane + 32) * KSTR + k];
#pragma unroll
            for (int i = 0; i < 8; i++) {
                float4 q = *(const float4*)&Qs[(r0 + i) * 128 + k];
                sv[i][0] += q.x * k0.x + q.y * k0.y + q.z * k0.z + q.w * k0.w;
                sv[i][1] += q.x * k1.x + q.y * k1.y + q.z * k1.z + q.w * k1.w;
            }
        }

        // Online softmax update (base-2; scale already folded into Q)
        const bool diag = (kt == qt);
#pragma unroll
        for (int i = 0; i < 8; i++) {
            float s0 = sv[i][0], s1 = sv[i][1];
            if (diag) {
                int rl = r0 + i;
                if (lane > rl)      s0 = -1e30f;
                if (lane + 32 > rl) s1 = -1e30f;
            }
            float mx = fmaxf(s0, s1);
#pragma unroll
            for (int off = 16; off > 0; off >>= 1)
                mx = fmaxf(mx, __shfl_xor_sync(0xffffffffu, mx, off));
            float mnew = fmaxf(mrow[i], mx);
            float corr = exp2f(mrow[i] - mnew);
            mrow[i] = mnew;
            float p0 = exp2f(s0 - mnew);
            float p1 = exp2f(s1 - mnew);
            float psum = p0 + p1;
#pragma unroll
            for (int off = 16; off > 0; off >>= 1)
                psum += __shfl_xor_sync(0xffffffffu, psum, off);
            lrow[i] = lrow[i] * corr + psum;
            o[i][0] *= corr; o[i][1] *= corr; o[i][2] *= corr; o[i][3] *= corr;
            Ps[(r0 + i) * PSTR + lane]      = p0;
            Ps[(r0 + i) * PSTR + lane + 32] = p1;
        }
        __syncwarp();   // P tile is warp-private (rows r0..r0+7): warp-scope fence is enough

        // GEMM2: O += P * V. Lane owns d-cols 4*lane..4*lane+3.
#pragma unroll 1
        for (int c = 0; c < 64; c += 4) {
            float4 v0 = *(const float4*)&Vs[(c + 0) * KSTR + lane * 4];
            float4 v1 = *(const float4*)&Vs[(c + 1) * KSTR + lane * 4];
            float4 v2 = *(const float4*)&Vs[(c + 2) * KSTR + lane * 4];
            float4 v3 = *(const float4*)&Vs[(c + 3) * KSTR + lane * 4];
#pragma unroll
            for (int i = 0; i < 8; i++) {
                float4 p = *(const float4*)&Ps[(r0 + i) * PSTR + c];
                o[i][0] += p.x * v0.x + p.y * v1.x + p.z * v2.x + p.w * v3.x;
                o[i][1] += p.x * v0.y + p.y * v1.y + p.z * v2.y + p.w * v3.y;
                o[i][2] += p.x * v0.z + p.y * v1.z + p.z * v2.z + p.w * v3.z;
                o[i][3] += p.x * v0.w + p.y * v1.w + p.z * v2.w + p.w * v3.w;
            }
        }
        __syncthreads();   // protect Ks/Vs before next tile load
    }

    // Normalize and write ctx [B*S, H*D]
#pragma unroll
    for (int i = 0; i < 8; i++) {
        float inv = 1.0f / lrow[i];
        float* dst = &g_ctx[(size_t)(b * S_LEN + qt * 64 + r0 + i) * HID + h * DHEAD + lane * 4];
        *(float4*)dst = make_float4(o[i][0] * inv, o[i][1] * inv, o[i][2] * inv, o[i][3] * inv);
    }
}

// ---------------------------------------------------------------------------
extern "C" void kernel_launch(void* const* d_in, const int* in_sizes, int n_in,
                              void* d_out, int out_size)
{
    const float* x  = (const float*)d_in[0];
    const float* Wq = (const float*)d_in[1];
    const float* Wk = (const float*)d_in[2];
    const float* Wv = (const float*)d_in[3];
    const float* Wo = (const float*)d_in[4];
    float* out = (float*)d_out;

    // Expected layout: [output (16.7M f32) | kv_cache (33.5M f32)].
    // If out_size disagrees, keep KV in device scratch so we never overflow d_out.
    const bool kv_in_out = ((size_t)out_size >= OUT_ELEMS + KV_ELEMS);
    float* kv = kv_in_out ? (out + OUT_ELEMS) : nullptr;

    dim3 gg(HID / 128, MROWS / 128);   // (16, 64)
    gemm_nt<<<gg, 256>>>(x, Wq, nullptr, MODE_Q);   // Q (scaled) -> g_qbuf
    gemm_nt<<<gg, 256>>>(x, Wk, kv, MODE_K);        // K -> kv cache layout
    gemm_nt<<<gg, 256>>>(x, Wv, kv, MODE_V);        // V -> kv cache layout

    cudaFuncSetAttribute(flash_attn, cudaFuncAttributeMaxDynamicSharedMemorySize,
                         SMEM_FLOATS * (int)sizeof(float));
    flash_attn<<<dim3(S_LEN / 64, HEADS, BATCH), 256, SMEM_FLOATS * sizeof(float)>>>(kv);

    gemm_nt<<<gg, 256>>>(nullptr, Wo, out, MODE_O); // ctx @ Wo^T -> output
}